// round 2
// baseline (speedup 1.0000x reference)
#include <cuda_runtime.h>
#include <cstdint>

// Problem constants
#define Bc 16
#define Sc 24
#define Lc 128
#define Dc 768
#define Ac 8
#define Tc 8
#define NSLOT 24          // 3 arg tensors * A=8
#define NST (NSLOT * Tc)  // 192 (slot, t) pairs

// SMEM layout (bytes)
//  acc      : NSLOT*Dc floats  = 73728
//  sid      : Lc ints          =   512
//  maskf    : Lc floats        =   512
//  bits     : Lc uints         =   512
//  argids   : NST ints         =   768
//  cnt192   : NST ints         =   768
//  chosen   : NSLOT ints       =    96
//  slotcnt  : NSLOT floats     =    96
#define SM_ACC     0
#define SM_SID     (SM_ACC + NSLOT * Dc * 4)
#define SM_MASKF   (SM_SID + Lc * 4)
#define SM_BITS    (SM_MASKF + Lc * 4)
#define SM_ARGIDS  (SM_BITS + Lc * 4)
#define SM_CNT192  (SM_ARGIDS + NST * 4)
#define SM_CHOSEN  (SM_CNT192 + NST * 4)
#define SM_SLOTCNT (SM_CHOSEN + NSLOT * 4)
#define SM_TOTAL   (SM_SLOTCNT + NSLOT * 4)   // 76992 bytes

__global__ __launch_bounds__(Dc, 2)
void srl_fused_kernel(const float* __restrict__ emb,
                      const int* __restrict__ masks,
                      const int* __restrict__ sids,
                      const int* __restrict__ pred_ids,
                      const int* __restrict__ arg0_ids,
                      const int* __restrict__ arg1_ids,
                      float* __restrict__ out)
{
    extern __shared__ char smem[];
    float*        s_acc     = (float*)(smem + SM_ACC);
    int*          s_sid     = (int*)(smem + SM_SID);
    float*        s_maskf   = (float*)(smem + SM_MASKF);
    unsigned int* s_bits    = (unsigned int*)(smem + SM_BITS);
    int*          s_argids  = (int*)(smem + SM_ARGIDS);
    int*          s_cnt192  = (int*)(smem + SM_CNT192);
    int*          s_chosen  = (int*)(smem + SM_CHOSEN);
    float*        s_slotcnt = (float*)(smem + SM_SLOTCNT);

    const int bs  = blockIdx.x;   // 0 .. B*S-1
    const int tid = threadIdx.x;  // 0 .. 767 (one D column per thread)

    // ---- zero slot accumulators (each thread owns its column across all slots)
    #pragma unroll
    for (int s = 0; s < NSLOT; s++)
        s_acc[s * Dc + tid] = 0.0f;

    // ---- stage tiny per-(b,s) metadata
    if (tid < Lc) {
        s_sid[tid]   = sids[bs * Lc + tid];
        s_maskf[tid] = (float)masks[bs * Lc + tid];
    }
    if (tid < NST) {
        // slot = type*8 + a ; t within slot
        int slot = tid / Tc;
        int t    = tid % Tc;
        int type = slot / Ac;
        int a    = slot % Ac;
        const int* src = (type == 0) ? pred_ids : (type == 1) ? arg0_ids : arg1_ids;
        s_argids[tid] = src[(bs * Ac + a) * Tc + t];
    }
    __syncthreads();

    // ---- per (slot,t) match counts over the sentence (192 threads, L-loop with
    //      broadcast LDS of s_sid)
    if (tid < NST) {
        int id = s_argids[tid];
        int c = 0;
        if (id != 0) {
            #pragma unroll 8
            for (int l = 0; l < Lc; l++) c += (s_sid[l] == id);
        }
        s_cnt192[tid] = c;
    }
    __syncthreads();

    // ---- per slot: last valid t -> chosen id + count
    if (tid < NSLOT) {
        int chosen = -1;
        float cf = 1.0f;
        #pragma unroll
        for (int t = Tc - 1; t >= 0; t--) {
            int c = s_cnt192[tid * Tc + t];
            if (c > 0) { chosen = s_argids[tid * Tc + t]; cf = (float)c; break; }
        }
        s_chosen[tid]  = chosen;
        s_slotcnt[tid] = cf;
    }
    __syncthreads();

    // ---- per-l slot match bitmask (chosen ids are never 0, never match -1)
    if (tid < Lc) {
        int sid = s_sid[tid];
        unsigned int bits = 0;
        #pragma unroll
        for (int s = 0; s < NSLOT; s++)
            bits |= (unsigned int)(s_chosen[s] == sid) << s;
        s_bits[tid] = bits;
    }
    __syncthreads();

    // ---- single fused streaming pass over the 128 x 768 embedding tile
    const float* ep = emb + (size_t)bs * Lc * Dc + tid;
    float accMean = 0.0f;
    float accCnt  = 0.0f;

    #pragma unroll 4
    for (int l = 0; l < Lc; l++) {
        float v  = __ldcs(ep + l * Dc);   // streaming: no reuse, evict-first
        float mf = s_maskf[l];            // broadcast LDS
        unsigned int bits = s_bits[l];    // uniform across CTA -> no divergence
        accMean = fmaf(v, mf, accMean);
        accCnt += mf;
        while (bits) {
            int s = __ffs(bits) - 1;
            bits &= bits - 1;
            s_acc[s * Dc + tid] += v;     // thread-private column, no conflict
        }
    }

    // ---- epilogue: mean pool output
    float cnt = fmaxf(accCnt, 1.0f);
    out[(size_t)bs * Dc + tid] = accMean / cnt;

    // ---- slot outputs (each thread only reads its own column: no sync needed)
    const size_t OFF0 = (size_t)Bc * Sc * Dc;        // 294912
    const size_t ASZ  = (size_t)Bc * Sc * Ac * Dc;   // 2359296
    #pragma unroll
    for (int s = 0; s < NSLOT; s++) {
        int type = s / Ac;
        int a    = s % Ac;
        float val = 0.0f;
        if (s_chosen[s] >= 0)
            val = s_acc[s * Dc + tid] / s_slotcnt[s];
        out[OFF0 + (size_t)type * ASZ + ((size_t)bs * Ac + a) * Dc + tid] = val;
    }
}

extern "C" void kernel_launch(void* const* d_in, const int* in_sizes, int n_in,
                              void* d_out, int out_size)
{
    const float* emb   = (const float*)d_in[0];  // [B,S,L,D] f32
    const int*   masks = (const int*)d_in[1];    // [B,S,L] i32
    const int*   sids  = (const int*)d_in[2];    // [B,S,L] i32
    const int*   pred  = (const int*)d_in[3];    // [B,S,A,T] i32
    const int*   a0    = (const int*)d_in[4];    // [B,S,A,T] i32
    const int*   a1    = (const int*)d_in[5];    // [B,S,A,T] i32
    float*       out   = (float*)d_out;

    // > 48KB dynamic smem needs the attribute; host-side, capture-safe, idempotent.
    cudaFuncSetAttribute(srl_fused_kernel,
                         cudaFuncAttributeMaxDynamicSharedMemorySize, SM_TOTAL);

    srl_fused_kernel<<<Bc * Sc, Dc, SM_TOTAL>>>(emb, masks, sids, pred, a0, a1, out);
}

// round 5
// speedup vs baseline: 1.3340x; 1.3340x over previous
#include <cuda_runtime.h>
#include <cstdint>

// Problem constants
#define Bc 16
#define Sc 24
#define Lc 128
#define Dc 768
#define Ac 8
#define Tc 8
#define NSLOT 24          // 3 arg tensors * A=8
#define NST (NSLOT * Tc)  // 192 (slot,t) pairs

#define DSPLIT 3          // columns split across blockIdx.y
#define CPT 2             // columns per thread (float2)
#define NTHR 128          // threads per CTA
#define COLS (NTHR * CPT) // 256 columns per CTA

// SMEM layout (bytes)
#define SM_ACC     0                              // NSLOT * NTHR float2 = 24576
#define SM_SID     (SM_ACC + NSLOT * NTHR * 8)    // Lc ints
#define SM_MASKF   (SM_SID + Lc * 4)              // Lc floats
#define SM_BITS    (SM_MASKF + Lc * 4)            // Lc uints
#define SM_ARGIDS  (SM_BITS + Lc * 4)             // NST ints
#define SM_CNT192  (SM_ARGIDS + NST * 4)          // NST ints
#define SM_CHOSEN  (SM_CNT192 + NST * 4)          // NSLOT ints
#define SM_SLOTCNT (SM_CHOSEN + NSLOT * 4)        // NSLOT floats
#define SM_TOTAL   (SM_SLOTCNT + NSLOT * 4)       // 27840 bytes

__global__ __launch_bounds__(NTHR, 8)
void srl_fused_kernel(const float* __restrict__ emb,
                      const int* __restrict__ masks,
                      const int* __restrict__ sids,
                      const int* __restrict__ pred_ids,
                      const int* __restrict__ arg0_ids,
                      const int* __restrict__ arg1_ids,
                      float* __restrict__ out)
{
    extern __shared__ char smem[];
    float2*       s_acc     = (float2*)(smem + SM_ACC);
    int*          s_sid     = (int*)(smem + SM_SID);
    float*        s_maskf   = (float*)(smem + SM_MASKF);
    unsigned int* s_bits    = (unsigned int*)(smem + SM_BITS);
    int*          s_argids  = (int*)(smem + SM_ARGIDS);
    int*          s_cnt192  = (int*)(smem + SM_CNT192);
    int*          s_chosen  = (int*)(smem + SM_CHOSEN);
    float*        s_slotcnt = (float*)(smem + SM_SLOTCNT);

    const int bs  = blockIdx.x;   // 0 .. B*S-1
    const int cy  = blockIdx.y;   // 0 .. DSPLIT-1
    const int tid = threadIdx.x;  // 0 .. 127

    // ---- zero slot accumulators (each thread owns its float2 column pair)
    #pragma unroll
    for (int s = 0; s < NSLOT; s++)
        s_acc[s * NTHR + tid] = make_float2(0.0f, 0.0f);

    // ---- stage tiny per-(b,s) metadata (Lc == NTHR == 128)
    s_sid[tid]   = sids[bs * Lc + tid];
    s_maskf[tid] = (float)masks[bs * Lc + tid];

    #pragma unroll
    for (int i = tid; i < NST; i += NTHR) {
        int slot = i / Tc;
        int t    = i % Tc;
        int type = slot / Ac;
        int a    = slot % Ac;
        const int* src = (type == 0) ? pred_ids : (type == 1) ? arg0_ids : arg1_ids;
        s_argids[i] = src[(bs * Ac + a) * Tc + t];
    }
    __syncthreads();

    // ---- per (slot,t) match counts over the sentence
    #pragma unroll
    for (int i = tid; i < NST; i += NTHR) {
        int id = s_argids[i];
        int c = 0;
        if (id != 0) {
            #pragma unroll 8
            for (int l = 0; l < Lc; l++) c += (s_sid[l] == id);
        }
        s_cnt192[i] = c;
    }
    __syncthreads();

    // ---- per slot: last valid t -> chosen id + count
    if (tid < NSLOT) {
        int chosen = -1;
        float cf = 1.0f;
        #pragma unroll
        for (int t = Tc - 1; t >= 0; t--) {
            int c = s_cnt192[tid * Tc + t];
            if (c > 0) { chosen = s_argids[tid * Tc + t]; cf = (float)c; break; }
        }
        s_chosen[tid]  = chosen;
        s_slotcnt[tid] = cf;
    }
    __syncthreads();

    // ---- per-l slot-match bitmask (chosen ids never 0, so never match -1)
    {
        int sid = s_sid[tid];
        unsigned int bits = 0;
        #pragma unroll
        for (int s = 0; s < NSLOT; s++)
            bits |= (unsigned int)(s_chosen[s] == sid) << s;
        s_bits[tid] = bits;
    }
    __syncthreads();

    // ---- fused streaming pass over the 128 x 256 column slice
    //      batched loads (8 x LDG.64 in flight) then process
    const float2* ep = (const float2*)(emb + (size_t)bs * Lc * Dc)
                       + cy * (COLS / 2) + tid;          // stride Dc/2 float2 per row
    float2 accM = make_float2(0.0f, 0.0f);
    float  accC = 0.0f;

    #pragma unroll 2
    for (int lb = 0; lb < Lc; lb += 8) {
        float2 v[8];
        #pragma unroll
        for (int i = 0; i < 8; i++)
            v[i] = ep[(size_t)(lb + i) * (Dc / 2)];

        #pragma unroll
        for (int i = 0; i < 8; i++) {
            int l = lb + i;
            float mf = s_maskf[l];
            accM.x = fmaf(v[i].x, mf, accM.x);
            accM.y = fmaf(v[i].y, mf, accM.y);
            accC += mf;
            unsigned int bits = s_bits[l];   // uniform across CTA -> no divergence
            while (bits) {
                int s = __ffs(bits) - 1;
                bits &= bits - 1;
                float2* a = &s_acc[s * NTHR + tid];   // thread-private, no conflict
                a->x += v[i].x;
                a->y += v[i].y;
            }
        }
    }

    // ---- outputs
    const int    colbase = cy * COLS + 2 * tid;
    const float  inv = 1.0f / fmaxf(accC, 1.0f);
    float2* outv;

    outv = (float2*)(out + (size_t)bs * Dc + colbase);
    *outv = make_float2(accM.x * inv, accM.y * inv);

    const size_t OFF0 = (size_t)Bc * Sc * Dc;        // mean-pool block size
    const size_t ASZ  = (size_t)Bc * Sc * Ac * Dc;   // per-arg-type block size
    #pragma unroll
    for (int s = 0; s < NSLOT; s++) {
        int type = s / Ac;
        int a    = s % Ac;
        float2 val = make_float2(0.0f, 0.0f);
        if (s_chosen[s] >= 0) {
            float invc = 1.0f / s_slotcnt[s];
            float2 acc = s_acc[s * NTHR + tid];
            val = make_float2(acc.x * invc, acc.y * invc);
        }
        outv = (float2*)(out + OFF0 + (size_t)type * ASZ
                         + ((size_t)bs * Ac + a) * Dc + colbase);
        *outv = val;
    }
}

extern "C" void kernel_launch(void* const* d_in, const int* in_sizes, int n_in,
                              void* d_out, int out_size)
{
    const float* emb   = (const float*)d_in[0];  // [B,S,L,D] f32
    const int*   masks = (const int*)d_in[1];    // [B,S,L] i32
    const int*   sids  = (const int*)d_in[2];    // [B,S,L] i32
    const int*   pred  = (const int*)d_in[3];    // [B,S,A,T] i32
    const int*   a0    = (const int*)d_in[4];    // [B,S,A,T] i32
    const int*   a1    = (const int*)d_in[5];    // [B,S,A,T] i32
    float*       out   = (float*)d_out;

    dim3 grid(Bc * Sc, DSPLIT);
    srl_fused_kernel<<<grid, NTHR, SM_TOTAL>>>(emb, masks, sids, pred, a0, a1, out);
}